// round 3
// baseline (speedup 1.0000x reference)
#include <cuda_runtime.h>
#include <cuda_bf16.h>

#define IMG_H 512
#define IMG_W 512
#define TW 64          // output tile width
#define TH 32          // output tile height
#define NT 256         // threads per block

// Shared tile dims per stage (each stage loses 1 halo ring)
#define SS_H (TH+8)    // 40  s = channel-summed input, halo 4
#define SS_W (TW+8)    // 72
#define SB_H (TH+6)    // 38  blurred, halo 3
#define SB_W (TW+6)    // 70
#define SG_H (TH+4)    // 36  grad magnitude, halo 2
#define SG_W (TW+4)    // 68
#define ST_H (TH+2)    // 34  directional-sum, halo 1
#define ST_W (TW+2)    // 66

__global__ __launch_bounds__(NT) void canny_fused(
    const float* __restrict__ img,     // (B,C,H,W)
    const float* __restrict__ gw,      // (C,1,3,3) identical per channel
    const float* __restrict__ sxw,     // (C,1,3,3)
    const float* __restrict__ syw,     // (C,1,3,3)
    const float* __restrict__ dw,      // (8,1,3,3)
    const float* __restrict__ nw,      // (1,8,3,3) identical per k
    float* __restrict__ out,           // (B,1,H,W)
    int C, float invC)
{
    __shared__ float sS[SS_H][SS_W + 1];
    __shared__ float sB[SB_H][SB_W + 1];
    __shared__ float sG[SG_H][SG_W + 1];
    __shared__ float sT[ST_H][ST_W + 1];
    __shared__ float wbuf[45];   // [0:9) gauss, [9:18) sobel_x, [18:27) sobel_y,
                                 // [27:36) D = sum_k dir_k, [36:45) nms pattern

    const int tid = threadIdx.x;
    const int b  = blockIdx.z;
    const int x0 = blockIdx.x * TW;
    const int y0 = blockIdx.y * TH;

    // ---- load weights (tiny) ----
    if (tid < 45) {
        float v;
        if (tid < 9)       v = gw[tid];
        else if (tid < 18) v = sxw[tid - 9];
        else if (tid < 27) v = syw[tid - 18];
        else if (tid < 36) {
            int j = tid - 27;
            v = 0.f;
            #pragma unroll
            for (int k = 0; k < 8; k++) v += dw[k * 9 + j];
        } else             v = nw[tid - 36];
        wbuf[tid] = v;
    }

    // ---- load s = sum over channels, with halo 4 (zero outside image) ----
    const float* ib = img + (size_t)b * C * IMG_H * IMG_W;
    for (int idx = tid; idx < SS_H * SS_W; idx += NT) {
        int r = idx / SS_W, c = idx - r * SS_W;
        int gy = y0 + r - 4, gx = x0 + c - 4;
        float v = 0.f;
        if (gy >= 0 && gy < IMG_H && gx >= 0 && gx < IMG_W) {
            const float* p = ib + gy * IMG_W + gx;
            v = p[0];
            for (int ch = 1; ch < C; ch++) v += p[(size_t)ch * IMG_H * IMG_W];
        }
        sS[r][c] = v;
    }
    __syncthreads();

    // ---- stage 1: gaussian blur (on s), clipped to image domain ----
    {
        float w[9];
        #pragma unroll
        for (int i = 0; i < 9; i++) w[i] = wbuf[i];
        for (int idx = tid; idx < SB_H * (SB_W / 2); idx += NT) {
            int r = idx / (SB_W / 2);
            int c = (idx - r * (SB_W / 2)) * 2;
            int gy = y0 + r - 3, gx = x0 + c - 3;
            float v0 = 0.f, v1 = 0.f;
            #pragma unroll
            for (int i = 0; i < 3; i++) {
                float a0 = sS[r + i][c], a1 = sS[r + i][c + 1];
                float a2 = sS[r + i][c + 2], a3 = sS[r + i][c + 3];
                v0 += w[i*3] * a0 + w[i*3+1] * a1 + w[i*3+2] * a2;
                v1 += w[i*3] * a1 + w[i*3+1] * a2 + w[i*3+2] * a3;
            }
            bool iny = (gy >= 0 && gy < IMG_H);
            sB[r][c]     = (iny && gx >= 0 && gx < IMG_W)     ? v0 : 0.f;
            sB[r][c + 1] = (iny && gx + 1 >= 0 && gx + 1 < IMG_W) ? v1 : 0.f;
        }
    }
    __syncthreads();

    // ---- stage 2: sobel x/y + magnitude, /C, clipped ----
    {
        float wx[9], wy[9];
        #pragma unroll
        for (int i = 0; i < 9; i++) { wx[i] = wbuf[9 + i]; wy[i] = wbuf[18 + i]; }
        for (int idx = tid; idx < SG_H * (SG_W / 2); idx += NT) {
            int r = idx / (SG_W / 2);
            int c = (idx - r * (SG_W / 2)) * 2;
            int gy = y0 + r - 2, gx = x0 + c - 2;
            float x0v = 0.f, y0v = 0.f, x1v = 0.f, y1v = 0.f;
            #pragma unroll
            for (int i = 0; i < 3; i++) {
                float a0 = sB[r + i][c], a1 = sB[r + i][c + 1];
                float a2 = sB[r + i][c + 2], a3 = sB[r + i][c + 3];
                x0v += wx[i*3] * a0 + wx[i*3+1] * a1 + wx[i*3+2] * a2;
                y0v += wy[i*3] * a0 + wy[i*3+1] * a1 + wy[i*3+2] * a2;
                x1v += wx[i*3] * a1 + wx[i*3+1] * a2 + wx[i*3+2] * a3;
                y1v += wy[i*3] * a1 + wy[i*3+1] * a2 + wy[i*3+2] * a3;
            }
            float v0 = sqrtf(x0v * x0v + y0v * y0v) * invC;
            float v1 = sqrtf(x1v * x1v + y1v * y1v) * invC;
            bool iny = (gy >= 0 && gy < IMG_H);
            sG[r][c]     = (iny && gx >= 0 && gx < IMG_W)     ? v0 : 0.f;
            sG[r][c + 1] = (iny && gx + 1 >= 0 && gx + 1 < IMG_W) ? v1 : 0.f;
        }
    }
    __syncthreads();

    // ---- stage 3: summed directional conv (D = sum_k dir_k), clipped ----
    {
        float w[9];
        #pragma unroll
        for (int i = 0; i < 9; i++) w[i] = wbuf[27 + i];
        for (int idx = tid; idx < ST_H * (ST_W / 2); idx += NT) {
            int r = idx / (ST_W / 2);
            int c = (idx - r * (ST_W / 2)) * 2;
            int gy = y0 + r - 1, gx = x0 + c - 1;
            float v0 = 0.f, v1 = 0.f;
            #pragma unroll
            for (int i = 0; i < 3; i++) {
                float a0 = sG[r + i][c], a1 = sG[r + i][c + 1];
                float a2 = sG[r + i][c + 2], a3 = sG[r + i][c + 3];
                v0 += w[i*3] * a0 + w[i*3+1] * a1 + w[i*3+2] * a2;
                v1 += w[i*3] * a1 + w[i*3+1] * a2 + w[i*3+2] * a3;
            }
            bool iny = (gy >= 0 && gy < IMG_H);
            sT[r][c]     = (iny && gx >= 0 && gx < IMG_W)     ? v0 : 0.f;
            sT[r][c + 1] = (iny && gx + 1 >= 0 && gx + 1 < IMG_W) ? v1 : 0.f;
        }
    }
    __syncthreads();

    // ---- stage 4: nms pattern conv -> output (always in-image) ----
    {
        float w[9];
        #pragma unroll
        for (int i = 0; i < 9; i++) w[i] = wbuf[36 + i];
        float* ob = out + (size_t)b * IMG_H * IMG_W;
        for (int idx = tid; idx < TH * (TW / 2); idx += NT) {
            int r = idx / (TW / 2);
            int c = (idx - r * (TW / 2)) * 2;
            float v0 = 0.f, v1 = 0.f;
            #pragma unroll
            for (int i = 0; i < 3; i++) {
                float a0 = sT[r + i][c], a1 = sT[r + i][c + 1];
                float a2 = sT[r + i][c + 2], a3 = sT[r + i][c + 3];
                v0 += w[i*3] * a0 + w[i*3+1] * a1 + w[i*3+2] * a2;
                v1 += w[i*3] * a1 + w[i*3+1] * a2 + w[i*3+2] * a3;
            }
            float2 res = make_float2(v0, v1);
            *reinterpret_cast<float2*>(ob + (size_t)(y0 + r) * IMG_W + x0 + c) = res;
        }
    }
}

extern "C" void kernel_launch(void* const* d_in, const int* in_sizes, int n_in,
                              void* d_out, int out_size) {
    const float* img = (const float*)d_in[0];
    const float* gw  = (const float*)d_in[1];
    const float* sxw = (const float*)d_in[2];
    const float* syw = (const float*)d_in[3];
    const float* dw  = (const float*)d_in[4];
    const float* nw  = (const float*)d_in[5];
    float* out = (float*)d_out;

    int C = in_sizes[1] / 9;                       // gauss_w is (C,1,3,3)
    if (C < 1) C = 1;
    int B = in_sizes[0] / (C * IMG_H * IMG_W);
    if (B < 1) B = 1;

    dim3 grid(IMG_W / TW, IMG_H / TH, B);
    canny_fused<<<grid, NT>>>(img, gw, sxw, syw, dw, nw, out, C, 1.0f / (float)C);
}

// round 5
// speedup vs baseline: 1.4500x; 1.4500x over previous
#include <cuda_runtime.h>
#include <cuda_bf16.h>

#define IMG_H 512
#define IMG_W 512
#define TW 64
#define TH 32
#define NT 256

// Padded row strides (floats, multiples of 4 for float4 alignment)
#define SP 76   // sS: 40 rows x 72 valid cols (halo 4)
#define BP 72   // sB: 38 rows x 70 valid cols (halo 3)
#define GP 72   // sG: 36 rows x 68 valid cols (halo 2)
#define TP 68   // sT: 34 rows x 66 valid cols (halo 1)

#define HW (IMG_H * IMG_W)

__global__ __launch_bounds__(NT, 5) void canny_fused(
    const float* __restrict__ img,     // (B,C,H,W)
    const float* __restrict__ gw,      // (C,1,3,3) identical per channel
    const float* __restrict__ sxw,     // (C,1,3,3)
    const float* __restrict__ syw,     // (C,1,3,3)
    const float* __restrict__ dw,      // (8,1,3,3)
    const float* __restrict__ nw,      // (1,8,3,3) identical per k
    float* __restrict__ out,           // (B,1,H,W)
    int C, float invC)
{
    // Aliased stage buffers: sS/sG share buf1, sB/sT share buf2 (disjoint lifetimes)
    __shared__ float buf1[40 * SP];            // max(40*76=3040, 36*72=2592)
    __shared__ float buf2[38 * BP];            // max(38*72=2736, 34*68=2312)
    __shared__ float wbuf[45];  // [0:9) gauss, [9:18) sobel_x, [18:27) sobel_y,
                                // [27:36) D = sum_k dir_k, [36:45) nms pattern

    float* const sS = buf1;
    float* const sB = buf2;
    float* const sG = buf1;
    float* const sT = buf2;

    const int tid = threadIdx.x;
    const int b  = blockIdx.z;
    const int x0 = blockIdx.x * TW;
    const int y0 = blockIdx.y * TH;

    // ---- weights ----
    if (tid < 45) {
        float v;
        if (tid < 9)       v = gw[tid];
        else if (tid < 18) v = sxw[tid - 9];
        else if (tid < 27) v = syw[tid - 18];
        else if (tid < 36) {
            int j = tid - 27;
            v = 0.f;
            #pragma unroll
            for (int k = 0; k < 8; k++) v += dw[k * 9 + j];
        } else             v = nw[tid - 36];
        wbuf[tid] = v;
    }

    // ---- load s = channel sum, halo 4 (zero outside image), float2 granularity ----
    {
        const float* ib = img + (size_t)b * C * HW;
        for (int it = tid; it < 40 * 36; it += NT) {
            int p = it / 36, q = it - p * 36;
            int py = y0 + p - 4;
            int px = x0 + q * 2 - 4;
            float v0 = 0.f, v1 = 0.f;
            if ((unsigned)py < (unsigned)IMG_H) {
                bool in0 = (unsigned)px < (unsigned)IMG_W;
                bool in1 = (unsigned)(px + 1) < (unsigned)IMG_W;
                const float* pp = ib + (size_t)py * IMG_W + px;
                if (in0 && in1) {
                    for (int ch = 0; ch < C; ch++) {
                        float2 t = *(const float2*)(pp + (size_t)ch * HW);
                        v0 += t.x; v1 += t.y;
                    }
                } else {
                    for (int ch = 0; ch < C; ch++) {
                        if (in0) v0 += pp[(size_t)ch * HW];
                        if (in1) v1 += pp[(size_t)ch * HW + 1];
                    }
                }
            }
            *(float2*)&sS[p * SP + q * 2] = make_float2(v0, v1);
        }
    }
    __syncthreads();

    // ---- stage 1: gaussian blur -> sB (halo 3), 4-wide x 2-high ----
    {
        float w[9];
        #pragma unroll
        for (int i = 0; i < 9; i++) w[i] = wbuf[i];
        for (int it = tid; it < 19 * 18; it += NT) {
            int rp = it / 18, g = it - rp * 18;
            int r = rp * 2, c = g * 4;
            float a[4][8];
            #pragma unroll
            for (int i = 0; i < 4; i++) {
                *(float4*)&a[i][0] = *(const float4*)&sS[(r + i) * SP + c];
                *(float4*)&a[i][4] = *(const float4*)&sS[(r + i) * SP + c + 4];
            }
            float v0[4] = {0.f,0.f,0.f,0.f}, v1[4] = {0.f,0.f,0.f,0.f};
            #pragma unroll
            for (int i = 0; i < 3; i++)
                #pragma unroll
                for (int j = 0; j < 4; j++) {
                    v0[j] += w[i*3]*a[i][j]   + w[i*3+1]*a[i][j+1]   + w[i*3+2]*a[i][j+2];
                    v1[j] += w[i*3]*a[i+1][j] + w[i*3+1]*a[i+1][j+1] + w[i*3+2]*a[i+1][j+2];
                }
            int py = y0 + r - 3, px = x0 + c - 3;
            bool iny0 = (unsigned)py       < (unsigned)IMG_H;
            bool iny1 = (unsigned)(py + 1) < (unsigned)IMG_H;
            #pragma unroll
            for (int j = 0; j < 4; j++) {
                bool inx = (unsigned)(px + j) < (unsigned)IMG_W;
                v0[j] = (iny0 && inx) ? v0[j] : 0.f;
                v1[j] = (iny1 && inx) ? v1[j] : 0.f;
            }
            *(float4*)&sB[r * BP + c]       = make_float4(v0[0], v0[1], v0[2], v0[3]);
            *(float4*)&sB[(r + 1) * BP + c] = make_float4(v1[0], v1[1], v1[2], v1[3]);
        }
    }
    __syncthreads();

    // ---- stage 2: sobel + magnitude -> sG (halo 2), 4-wide x 1-high ----
    {
        float wx[9], wy[9];
        #pragma unroll
        for (int i = 0; i < 9; i++) { wx[i] = wbuf[9 + i]; wy[i] = wbuf[18 + i]; }
        for (int it = tid; it < 36 * 17; it += NT) {
            int r = it / 17, g = it - r * 17;
            int c = g * 4;
            float a[3][8];
            #pragma unroll
            for (int i = 0; i < 3; i++) {
                *(float4*)&a[i][0] = *(const float4*)&sB[(r + i) * BP + c];
                *(float4*)&a[i][4] = *(const float4*)&sB[(r + i) * BP + c + 4];
            }
            float gx[4] = {0.f,0.f,0.f,0.f}, gy[4] = {0.f,0.f,0.f,0.f};
            #pragma unroll
            for (int i = 0; i < 3; i++)
                #pragma unroll
                for (int j = 0; j < 4; j++) {
                    gx[j] += wx[i*3]*a[i][j] + wx[i*3+1]*a[i][j+1] + wx[i*3+2]*a[i][j+2];
                    gy[j] += wy[i*3]*a[i][j] + wy[i*3+1]*a[i][j+1] + wy[i*3+2]*a[i][j+2];
                }
            int py = y0 + r - 2, px = x0 + c - 2;
            bool iny = (unsigned)py < (unsigned)IMG_H;
            float v[4];
            #pragma unroll
            for (int j = 0; j < 4; j++) {
                float m = sqrtf(gx[j]*gx[j] + gy[j]*gy[j]) * invC;
                bool inx = (unsigned)(px + j) < (unsigned)IMG_W;
                v[j] = (iny && inx) ? m : 0.f;
            }
            *(float4*)&sG[r * GP + c] = make_float4(v[0], v[1], v[2], v[3]);
        }
    }
    __syncthreads();

    // ---- stage 3: summed directional conv -> sT (halo 1), 4-wide x 2-high ----
    {
        float w[9];
        #pragma unroll
        for (int i = 0; i < 9; i++) w[i] = wbuf[27 + i];
        for (int it = tid; it < 17 * 17; it += NT) {
            int rp = it / 17, g = it - rp * 17;
            int r = rp * 2, c = g * 4;
            float a[4][8];
            #pragma unroll
            for (int i = 0; i < 4; i++) {
                *(float4*)&a[i][0] = *(const float4*)&sG[(r + i) * GP + c];
                *(float4*)&a[i][4] = *(const float4*)&sG[(r + i) * GP + c + 4];
            }
            float v0[4] = {0.f,0.f,0.f,0.f}, v1[4] = {0.f,0.f,0.f,0.f};
            #pragma unroll
            for (int i = 0; i < 3; i++)
                #pragma unroll
                for (int j = 0; j < 4; j++) {
                    v0[j] += w[i*3]*a[i][j]   + w[i*3+1]*a[i][j+1]   + w[i*3+2]*a[i][j+2];
                    v1[j] += w[i*3]*a[i+1][j] + w[i*3+1]*a[i+1][j+1] + w[i*3+2]*a[i+1][j+2];
                }
            int py = y0 + r - 1, px = x0 + c - 1;
            bool iny0 = (unsigned)py       < (unsigned)IMG_H;
            bool iny1 = (unsigned)(py + 1) < (unsigned)IMG_H;
            #pragma unroll
            for (int j = 0; j < 4; j++) {
                bool inx = (unsigned)(px + j) < (unsigned)IMG_W;
                v0[j] = (iny0 && inx) ? v0[j] : 0.f;
                v1[j] = (iny1 && inx) ? v1[j] : 0.f;
            }
            *(float4*)&sT[r * TP + c]       = make_float4(v0[0], v0[1], v0[2], v0[3]);
            *(float4*)&sT[(r + 1) * TP + c] = make_float4(v1[0], v1[1], v1[2], v1[3]);
        }
    }
    __syncthreads();

    // ---- stage 4: nms pattern conv -> out, 4-wide x 2-high (exactly 1 item/thread) ----
    {
        float w[9];
        #pragma unroll
        for (int i = 0; i < 9; i++) w[i] = wbuf[36 + i];
        int rp = tid >> 4, g = tid & 15;     // 16 row-pairs x 16 col-groups = 256
        int r = rp * 2, c = g * 4;
        float a[4][8];
        #pragma unroll
        for (int i = 0; i < 4; i++) {
            *(float4*)&a[i][0] = *(const float4*)&sT[(r + i) * TP + c];
            *(float4*)&a[i][4] = *(const float4*)&sT[(r + i) * TP + c + 4];
        }
        float v0[4] = {0.f,0.f,0.f,0.f}, v1[4] = {0.f,0.f,0.f,0.f};
        #pragma unroll
        for (int i = 0; i < 3; i++)
            #pragma unroll
            for (int j = 0; j < 4; j++) {
                v0[j] += w[i*3]*a[i][j]   + w[i*3+1]*a[i][j+1]   + w[i*3+2]*a[i][j+2];
                v1[j] += w[i*3]*a[i+1][j] + w[i*3+1]*a[i+1][j+1] + w[i*3+2]*a[i+1][j+2];
            }
        float* ob = out + (size_t)b * HW + (size_t)(y0 + r) * IMG_W + x0 + c;
        *(float4*)ob            = make_float4(v0[0], v0[1], v0[2], v0[3]);
        *(float4*)(ob + IMG_W)  = make_float4(v1[0], v1[1], v1[2], v1[3]);
    }
}

extern "C" void kernel_launch(void* const* d_in, const int* in_sizes, int n_in,
                              void* d_out, int out_size) {
    const float* img = (const float*)d_in[0];
    const float* gw  = (const float*)d_in[1];
    const float* sxw = (const float*)d_in[2];
    const float* syw = (const float*)d_in[3];
    const float* dw  = (const float*)d_in[4];
    const float* nw  = (const float*)d_in[5];
    float* out = (float*)d_out;

    int C = in_sizes[1] / 9;
    if (C < 1) C = 1;
    int B = in_sizes[0] / (C * HW);
    if (B < 1) B = 1;

    dim3 grid(IMG_W / TW, IMG_H / TH, B);
    canny_fused<<<grid, NT>>>(img, gw, sxw, syw, dw, nw, out, C, 1.0f / (float)C);
}

// round 6
// speedup vs baseline: 1.6585x; 1.1437x over previous
#include <cuda_runtime.h>
#include <cuda_bf16.h>

#define IMG_H 512
#define IMG_W 512
#define TW 64
#define TH 32
#define NT 256

// Padded row strides (floats); sized so every 12-float read stays inside a row.
#define SP 76   // sS: 40 rows x 76 cols written (72 valid, halo 4)
#define BP 76   // sB: 38 rows x 72 cols written (70 valid, halo 3)
#define GP 76   // sG: 36 rows x 68 cols written (68 valid, halo 2)
#define TP 72   // sT: 34 rows x 72 cols written (66 valid, halo 1)

#define HW (IMG_H * IMG_W)

__global__ __launch_bounds__(NT, 5) void canny_fused(
    const float* __restrict__ img,     // (B,C,H,W)
    const float* __restrict__ gw,      // (C,1,3,3) identical per channel
    const float* __restrict__ sxw,     // (C,1,3,3)
    const float* __restrict__ syw,     // (C,1,3,3)
    const float* __restrict__ dw,      // (8,1,3,3)
    const float* __restrict__ nw,      // (1,8,3,3) identical per k
    float* __restrict__ out,           // (B,1,H,W)
    int C, float invC)
{
    // Aliased stage buffers: sS/sG share buf1, sB/sT share buf2 (disjoint lifetimes)
    __shared__ float buf1[40 * SP];            // sS 40x76=3040, sG 36x76=2736
    __shared__ float buf2[38 * BP];            // sB 38x76=2888, sT 34x72=2448
    __shared__ float wbuf[45];  // [0:9) gauss, [9:18) sobel_x, [18:27) sobel_y,
                                // [27:36) D = sum_k dir_k, [36:45) nms pattern

    float* const sS = buf1;
    float* const sB = buf2;
    float* const sG = buf1;
    float* const sT = buf2;

    const int tid = threadIdx.x;
    const int b  = blockIdx.z;
    const int x0 = blockIdx.x * TW;
    const int y0 = blockIdx.y * TH;

    // ---- weights ----
    if (tid < 45) {
        float v;
        if (tid < 9)       v = gw[tid];
        else if (tid < 18) v = sxw[tid - 9];
        else if (tid < 27) v = syw[tid - 18];
        else if (tid < 36) {
            int j = tid - 27;
            v = 0.f;
            #pragma unroll
            for (int k = 0; k < 8; k++) v += dw[k * 9 + j];
        } else             v = nw[tid - 36];
        wbuf[tid] = v;
    }

    // ---- load s = channel sum, halo 4 (zero outside image), float4 granularity ----
    {
        const float* ib = img + (size_t)b * C * HW;
        for (int it = tid; it < 40 * 19; it += NT) {
            int p = it / 19, q = it - p * 19;
            int py = y0 + p - 4;
            int px = x0 + q * 4 - 4;
            float v[4] = {0.f, 0.f, 0.f, 0.f};
            if ((unsigned)py < (unsigned)IMG_H) {
                if (px >= 0 && px + 3 < IMG_W) {
                    const float* pp = ib + (size_t)py * IMG_W + px;
                    for (int ch = 0; ch < C; ch++) {
                        float4 t = *(const float4*)(pp + (size_t)ch * HW);
                        v[0] += t.x; v[1] += t.y; v[2] += t.z; v[3] += t.w;
                    }
                } else {
                    #pragma unroll
                    for (int j = 0; j < 4; j++) {
                        int xx = px + j;
                        if ((unsigned)xx < (unsigned)IMG_W) {
                            float s = 0.f;
                            for (int ch = 0; ch < C; ch++)
                                s += ib[(size_t)ch * HW + (size_t)py * IMG_W + xx];
                            v[j] = s;
                        }
                    }
                }
            }
            *(float4*)&sS[p * SP + q * 4] = make_float4(v[0], v[1], v[2], v[3]);
        }
    }
    __syncthreads();

    // ---- stage 1: gaussian blur -> sB (halo 3), 8-wide x 2-high, row-streamed ----
    if (tid < 19 * 9) {
        float w[9];
        #pragma unroll
        for (int i = 0; i < 9; i++) w[i] = wbuf[i];
        int rp = tid / 9, g = tid - rp * 9;
        int r = rp * 2, c = g * 8;
        float v0[8] = {0,0,0,0,0,0,0,0}, v1[8] = {0,0,0,0,0,0,0,0};
        #pragma unroll
        for (int i = 0; i < 4; i++) {
            float t[12];
            *(float4*)&t[0] = *(const float4*)&sS[(r + i) * SP + c];
            *(float4*)&t[4] = *(const float4*)&sS[(r + i) * SP + c + 4];
            *(float4*)&t[8] = *(const float4*)&sS[(r + i) * SP + c + 8];
            if (i < 3) {
                #pragma unroll
                for (int j = 0; j < 8; j++)
                    v0[j] += w[i*3]*t[j] + w[i*3+1]*t[j+1] + w[i*3+2]*t[j+2];
            }
            if (i > 0) {
                #pragma unroll
                for (int j = 0; j < 8; j++)
                    v1[j] += w[(i-1)*3]*t[j] + w[(i-1)*3+1]*t[j+1] + w[(i-1)*3+2]*t[j+2];
            }
        }
        int py = y0 + r - 3, px = x0 + c - 3;
        bool iny0 = (unsigned)py       < (unsigned)IMG_H;
        bool iny1 = (unsigned)(py + 1) < (unsigned)IMG_H;
        #pragma unroll
        for (int j = 0; j < 8; j++) {
            bool inx = (unsigned)(px + j) < (unsigned)IMG_W;
            v0[j] = (iny0 && inx) ? v0[j] : 0.f;
            v1[j] = (iny1 && inx) ? v1[j] : 0.f;
        }
        *(float4*)&sB[r * BP + c]           = make_float4(v0[0], v0[1], v0[2], v0[3]);
        *(float4*)&sB[r * BP + c + 4]       = make_float4(v0[4], v0[5], v0[6], v0[7]);
        *(float4*)&sB[(r + 1) * BP + c]     = make_float4(v1[0], v1[1], v1[2], v1[3]);
        *(float4*)&sB[(r + 1) * BP + c + 4] = make_float4(v1[4], v1[5], v1[6], v1[7]);
    }
    __syncthreads();

    // ---- stage 2: sobel + magnitude -> sG (halo 2), 4-wide x 2-high, row-streamed ----
    {
        float wx[9], wy[9];
        #pragma unroll
        for (int i = 0; i < 9; i++) { wx[i] = wbuf[9 + i]; wy[i] = wbuf[18 + i]; }
        for (int it = tid; it < 18 * 17; it += NT) {
            int rp = it / 17, g = it - rp * 17;
            int r = rp * 2, c = g * 4;
            float gx0[4] = {0,0,0,0}, gy0[4] = {0,0,0,0};
            float gx1[4] = {0,0,0,0}, gy1[4] = {0,0,0,0};
            #pragma unroll
            for (int i = 0; i < 4; i++) {
                float t[8];
                *(float4*)&t[0] = *(const float4*)&sB[(r + i) * BP + c];
                *(float4*)&t[4] = *(const float4*)&sB[(r + i) * BP + c + 4];
                if (i < 3) {
                    #pragma unroll
                    for (int j = 0; j < 4; j++) {
                        gx0[j] += wx[i*3]*t[j] + wx[i*3+1]*t[j+1] + wx[i*3+2]*t[j+2];
                        gy0[j] += wy[i*3]*t[j] + wy[i*3+1]*t[j+1] + wy[i*3+2]*t[j+2];
                    }
                }
                if (i > 0) {
                    #pragma unroll
                    for (int j = 0; j < 4; j++) {
                        gx1[j] += wx[(i-1)*3]*t[j] + wx[(i-1)*3+1]*t[j+1] + wx[(i-1)*3+2]*t[j+2];
                        gy1[j] += wy[(i-1)*3]*t[j] + wy[(i-1)*3+1]*t[j+1] + wy[(i-1)*3+2]*t[j+2];
                    }
                }
            }
            int py = y0 + r - 2, px = x0 + c - 2;
            bool iny0 = (unsigned)py       < (unsigned)IMG_H;
            bool iny1 = (unsigned)(py + 1) < (unsigned)IMG_H;
            float v0[4], v1[4];
            #pragma unroll
            for (int j = 0; j < 4; j++) {
                bool inx = (unsigned)(px + j) < (unsigned)IMG_W;
                float m0 = sqrtf(gx0[j]*gx0[j] + gy0[j]*gy0[j]) * invC;
                float m1 = sqrtf(gx1[j]*gx1[j] + gy1[j]*gy1[j]) * invC;
                v0[j] = (iny0 && inx) ? m0 : 0.f;
                v1[j] = (iny1 && inx) ? m1 : 0.f;
            }
            *(float4*)&sG[r * GP + c]       = make_float4(v0[0], v0[1], v0[2], v0[3]);
            *(float4*)&sG[(r + 1) * GP + c] = make_float4(v1[0], v1[1], v1[2], v1[3]);
        }
    }
    __syncthreads();

    // ---- stage 3: summed directional conv -> sT (halo 1), 8-wide x 2-high ----
    if (tid < 17 * 9) {
        float w[9];
        #pragma unroll
        for (int i = 0; i < 9; i++) w[i] = wbuf[27 + i];
        int rp = tid / 9, g = tid - rp * 9;
        int r = rp * 2, c = g * 8;
        float v0[8] = {0,0,0,0,0,0,0,0}, v1[8] = {0,0,0,0,0,0,0,0};
        #pragma unroll
        for (int i = 0; i < 4; i++) {
            float t[12];
            *(float4*)&t[0] = *(const float4*)&sG[(r + i) * GP + c];
            *(float4*)&t[4] = *(const float4*)&sG[(r + i) * GP + c + 4];
            *(float4*)&t[8] = *(const float4*)&sG[(r + i) * GP + c + 8];
            if (i < 3) {
                #pragma unroll
                for (int j = 0; j < 8; j++)
                    v0[j] += w[i*3]*t[j] + w[i*3+1]*t[j+1] + w[i*3+2]*t[j+2];
            }
            if (i > 0) {
                #pragma unroll
                for (int j = 0; j < 8; j++)
                    v1[j] += w[(i-1)*3]*t[j] + w[(i-1)*3+1]*t[j+1] + w[(i-1)*3+2]*t[j+2];
            }
        }
        int py = y0 + r - 1, px = x0 + c - 1;
        bool iny0 = (unsigned)py       < (unsigned)IMG_H;
        bool iny1 = (unsigned)(py + 1) < (unsigned)IMG_H;
        #pragma unroll
        for (int j = 0; j < 8; j++) {
            bool inx = (unsigned)(px + j) < (unsigned)IMG_W;
            v0[j] = (iny0 && inx) ? v0[j] : 0.f;
            v1[j] = (iny1 && inx) ? v1[j] : 0.f;
        }
        *(float4*)&sT[r * TP + c]           = make_float4(v0[0], v0[1], v0[2], v0[3]);
        *(float4*)&sT[r * TP + c + 4]       = make_float4(v0[4], v0[5], v0[6], v0[7]);
        *(float4*)&sT[(r + 1) * TP + c]     = make_float4(v1[0], v1[1], v1[2], v1[3]);
        *(float4*)&sT[(r + 1) * TP + c + 4] = make_float4(v1[4], v1[5], v1[6], v1[7]);
    }
    __syncthreads();

    // ---- stage 4: nms pattern conv -> out, 8-wide x 2-high (128 active threads) ----
    if (tid < 16 * 8) {
        float w[9];
        #pragma unroll
        for (int i = 0; i < 9; i++) w[i] = wbuf[36 + i];
        int rp = tid >> 3, g = tid & 7;
        int r = rp * 2, c = g * 8;
        float v0[8] = {0,0,0,0,0,0,0,0}, v1[8] = {0,0,0,0,0,0,0,0};
        #pragma unroll
        for (int i = 0; i < 4; i++) {
            float t[12];
            *(float4*)&t[0] = *(const float4*)&sT[(r + i) * TP + c];
            *(float4*)&t[4] = *(const float4*)&sT[(r + i) * TP + c + 4];
            *(float4*)&t[8] = *(const float4*)&sT[(r + i) * TP + c + 8];
            if (i < 3) {
                #pragma unroll
                for (int j = 0; j < 8; j++)
                    v0[j] += w[i*3]*t[j] + w[i*3+1]*t[j+1] + w[i*3+2]*t[j+2];
            }
            if (i > 0) {
                #pragma unroll
                for (int j = 0; j < 8; j++)
                    v1[j] += w[(i-1)*3]*t[j] + w[(i-1)*3+1]*t[j+1] + w[(i-1)*3+2]*t[j+2];
            }
        }
        float* ob = out + (size_t)b * HW + (size_t)(y0 + r) * IMG_W + x0 + c;
        *(float4*)ob                 = make_float4(v0[0], v0[1], v0[2], v0[3]);
        *(float4*)(ob + 4)           = make_float4(v0[4], v0[5], v0[6], v0[7]);
        *(float4*)(ob + IMG_W)       = make_float4(v1[0], v1[1], v1[2], v1[3]);
        *(float4*)(ob + IMG_W + 4)   = make_float4(v1[4], v1[5], v1[6], v1[7]);
    }
}

extern "C" void kernel_launch(void* const* d_in, const int* in_sizes, int n_in,
                              void* d_out, int out_size) {
    const float* img = (const float*)d_in[0];
    const float* gw  = (const float*)d_in[1];
    const float* sxw = (const float*)d_in[2];
    const float* syw = (const float*)d_in[3];
    const float* dw  = (const float*)d_in[4];
    const float* nw  = (const float*)d_in[5];
    float* out = (float*)d_out;

    int C = in_sizes[1] / 9;
    if (C < 1) C = 1;
    int B = in_sizes[0] / (C * HW);
    if (B < 1) B = 1;

    dim3 grid(IMG_W / TW, IMG_H / TH, B);
    canny_fused<<<grid, NT>>>(img, gw, sxw, syw, dw, nw, out, C, 1.0f / (float)C);
}

// round 7
// speedup vs baseline: 1.7239x; 1.0394x over previous
#include <cuda_runtime.h>
#include <cuda_bf16.h>

#define IMG_H 512
#define IMG_W 512
#define TW 64
#define TH 32
#define NT 256

// Padded row strides (floats); sized so every 12-float read stays inside a row.
#define SP 76   // sS: 40 rows (72 valid cols, halo 4)
#define BP 76   // sB: 38 rows (70 valid cols, halo 3)
#define GP 76   // sG: 36 rows (68 valid cols, halo 2)
#define TP 72   // sT: 34 rows (66 valid cols, halo 1)  [border path only]

#define HW (IMG_H * IMG_W)

__global__ __launch_bounds__(NT, 5) void canny_fused(
    const float* __restrict__ img,     // (B,C,H,W)
    const float* __restrict__ gw,      // (C,1,3,3) identical per channel
    const float* __restrict__ sxw,     // (C,1,3,3)
    const float* __restrict__ syw,     // (C,1,3,3)
    const float* __restrict__ dw,      // (8,1,3,3)
    const float* __restrict__ nw,      // (1,8,3,3) identical per k
    float* __restrict__ out,           // (B,1,H,W)
    int C, float invC)
{
    // Aliased stage buffers: sS/sG share buf1, sB/sT share buf2 (disjoint lifetimes)
    __shared__ float buf1[40 * SP];
    __shared__ float buf2[38 * BP];
    __shared__ float wbuf[70];  // [0:9) gauss, [9:18) sobel_x, [18:27) sobel_y,
                                // [27:36) D = sum_k dir_k, [36:45) nms pattern P,
                                // [45:70) W5 = full_conv2(D, P)  (5x5 composite)

    float* const sS = buf1;
    float* const sB = buf2;
    float* const sG = buf1;
    float* const sT = buf2;

    const int tid = threadIdx.x;
    const int b  = blockIdx.z;
    const int x0 = blockIdx.x * TW;
    const int y0 = blockIdx.y * TH;
    const bool interior = (x0 > 0) && (x0 + TW < IMG_W) && (y0 > 0) && (y0 + TH < IMG_H);

    // ---- weights ----
    if (tid < 45) {
        float v;
        if (tid < 9)       v = gw[tid];
        else if (tid < 18) v = sxw[tid - 9];
        else if (tid < 27) v = syw[tid - 18];
        else if (tid < 36) {
            int j = tid - 27;
            v = 0.f;
            #pragma unroll
            for (int k = 0; k < 8; k++) v += dw[k * 9 + j];
        } else             v = nw[tid - 36];
        wbuf[tid] = v;
    }

    // ---- load s = channel sum, halo 4 (zero outside image), float4 granularity ----
    {
        const float* ib = img + (size_t)b * C * HW;
        for (int it = tid; it < 40 * 19; it += NT) {
            int p = it / 19, q = it - p * 19;
            int py = y0 + p - 4;
            int px = x0 + q * 4 - 4;
            float v[4] = {0.f, 0.f, 0.f, 0.f};
            if ((unsigned)py < (unsigned)IMG_H) {
                if (px >= 0 && px + 3 < IMG_W) {
                    const float* pp = ib + (size_t)py * IMG_W + px;
                    for (int ch = 0; ch < C; ch++) {
                        float4 t = *(const float4*)(pp + (size_t)ch * HW);
                        v[0] += t.x; v[1] += t.y; v[2] += t.z; v[3] += t.w;
                    }
                } else {
                    #pragma unroll
                    for (int j = 0; j < 4; j++) {
                        int xx = px + j;
                        if ((unsigned)xx < (unsigned)IMG_W) {
                            float s = 0.f;
                            for (int ch = 0; ch < C; ch++)
                                s += ib[(size_t)ch * HW + (size_t)py * IMG_W + xx];
                            v[j] = s;
                        }
                    }
                }
            }
            *(float4*)&sS[p * SP + q * 4] = make_float4(v[0], v[1], v[2], v[3]);
        }
    }
    __syncthreads();

    // ---- composite W5 = full_conv2(D, P), 25 threads (ready before next sync) ----
    if (tid < 25) {
        int a = tid / 5, bb = tid - a * 5;
        float s = 0.f;
        #pragma unroll
        for (int i = 0; i < 3; i++)
            #pragma unroll
            for (int j = 0; j < 3; j++) {
                int u = a - i, v = bb - j;
                if (u >= 0 && u < 3 && v >= 0 && v < 3)
                    s += wbuf[27 + i * 3 + j] * wbuf[36 + u * 3 + v];
            }
        wbuf[45 + tid] = s;
    }

    // ---- stage 1: gaussian blur -> sB (halo 3), 8-wide x 2-high, row-streamed ----
    if (tid < 19 * 9) {
        float w[9];
        #pragma unroll
        for (int i = 0; i < 9; i++) w[i] = wbuf[i];
        int rp = tid / 9, g = tid - rp * 9;
        int r = rp * 2, c = g * 8;
        float v0[8] = {0,0,0,0,0,0,0,0}, v1[8] = {0,0,0,0,0,0,0,0};
        #pragma unroll
        for (int i = 0; i < 4; i++) {
            float t[12];
            *(float4*)&t[0] = *(const float4*)&sS[(r + i) * SP + c];
            *(float4*)&t[4] = *(const float4*)&sS[(r + i) * SP + c + 4];
            *(float4*)&t[8] = *(const float4*)&sS[(r + i) * SP + c + 8];
            if (i < 3) {
                #pragma unroll
                for (int j = 0; j < 8; j++)
                    v0[j] += w[i*3]*t[j] + w[i*3+1]*t[j+1] + w[i*3+2]*t[j+2];
            }
            if (i > 0) {
                #pragma unroll
                for (int j = 0; j < 8; j++)
                    v1[j] += w[(i-1)*3]*t[j] + w[(i-1)*3+1]*t[j+1] + w[(i-1)*3+2]*t[j+2];
            }
        }
        int py = y0 + r - 3, px = x0 + c - 3;
        bool iny0 = (unsigned)py       < (unsigned)IMG_H;
        bool iny1 = (unsigned)(py + 1) < (unsigned)IMG_H;
        #pragma unroll
        for (int j = 0; j < 8; j++) {
            bool inx = (unsigned)(px + j) < (unsigned)IMG_W;
            v0[j] = (iny0 && inx) ? v0[j] : 0.f;
            v1[j] = (iny1 && inx) ? v1[j] : 0.f;
        }
        *(float4*)&sB[r * BP + c]           = make_float4(v0[0], v0[1], v0[2], v0[3]);
        *(float4*)&sB[r * BP + c + 4]       = make_float4(v0[4], v0[5], v0[6], v0[7]);
        *(float4*)&sB[(r + 1) * BP + c]     = make_float4(v1[0], v1[1], v1[2], v1[3]);
        *(float4*)&sB[(r + 1) * BP + c + 4] = make_float4(v1[4], v1[5], v1[6], v1[7]);
    }
    __syncthreads();

    // ---- stage 2: sobel + magnitude -> sG (halo 2), 4-wide x 2-high ----
    {
        float wx[9], wy[9];
        #pragma unroll
        for (int i = 0; i < 9; i++) { wx[i] = wbuf[9 + i]; wy[i] = wbuf[18 + i]; }
        for (int it = tid; it < 18 * 17; it += NT) {
            int rp = it / 17, g = it - rp * 17;
            int r = rp * 2, c = g * 4;
            float gx0[4] = {0,0,0,0}, gy0[4] = {0,0,0,0};
            float gx1[4] = {0,0,0,0}, gy1[4] = {0,0,0,0};
            #pragma unroll
            for (int i = 0; i < 4; i++) {
                float t[8];
                *(float4*)&t[0] = *(const float4*)&sB[(r + i) * BP + c];
                *(float4*)&t[4] = *(const float4*)&sB[(r + i) * BP + c + 4];
                if (i < 3) {
                    #pragma unroll
                    for (int j = 0; j < 4; j++) {
                        gx0[j] += wx[i*3]*t[j] + wx[i*3+1]*t[j+1] + wx[i*3+2]*t[j+2];
                        gy0[j] += wy[i*3]*t[j] + wy[i*3+1]*t[j+1] + wy[i*3+2]*t[j+2];
                    }
                }
                if (i > 0) {
                    #pragma unroll
                    for (int j = 0; j < 4; j++) {
                        gx1[j] += wx[(i-1)*3]*t[j] + wx[(i-1)*3+1]*t[j+1] + wx[(i-1)*3+2]*t[j+2];
                        gy1[j] += wy[(i-1)*3]*t[j] + wy[(i-1)*3+1]*t[j+1] + wy[(i-1)*3+2]*t[j+2];
                    }
                }
            }
            int py = y0 + r - 2, px = x0 + c - 2;
            bool iny0 = (unsigned)py       < (unsigned)IMG_H;
            bool iny1 = (unsigned)(py + 1) < (unsigned)IMG_H;
            float v0[4], v1[4];
            #pragma unroll
            for (int j = 0; j < 4; j++) {
                bool inx = (unsigned)(px + j) < (unsigned)IMG_W;
                float m0 = sqrtf(gx0[j]*gx0[j] + gy0[j]*gy0[j]) * invC;
                float m1 = sqrtf(gx1[j]*gx1[j] + gy1[j]*gy1[j]) * invC;
                v0[j] = (iny0 && inx) ? m0 : 0.f;
                v1[j] = (iny1 && inx) ? m1 : 0.f;
            }
            *(float4*)&sG[r * GP + c]       = make_float4(v0[0], v0[1], v0[2], v0[3]);
            *(float4*)&sG[(r + 1) * GP + c] = make_float4(v1[0], v1[1], v1[2], v1[3]);
        }
    }
    __syncthreads();

    if (interior) {
        // ---- stage C: 5x5 composite W5 = D*P over sG -> out, 8-wide x 2-high ----
        if (tid < 16 * 8) {
            int rp = tid >> 3, g = tid & 7;
            int r = rp * 2, c = g * 8;
            float o0[8] = {0,0,0,0,0,0,0,0}, o1[8] = {0,0,0,0,0,0,0,0};
            float wp[5];
            #pragma unroll
            for (int i = 0; i < 6; i++) {
                float t[12];
                *(float4*)&t[0] = *(const float4*)&sG[(r + i) * GP + c];
                *(float4*)&t[4] = *(const float4*)&sG[(r + i) * GP + c + 4];
                *(float4*)&t[8] = *(const float4*)&sG[(r + i) * GP + c + 8];
                if (i > 0) {
                    #pragma unroll
                    for (int j = 0; j < 8; j++) {
                        float s = wp[0]*t[j] + wp[1]*t[j+1] + wp[2]*t[j+2]
                                + wp[3]*t[j+3] + wp[4]*t[j+4];
                        o1[j] += s;
                    }
                }
                if (i < 5) {
                    float wc[5];
                    #pragma unroll
                    for (int v = 0; v < 5; v++) wc[v] = wbuf[45 + i * 5 + v];
                    #pragma unroll
                    for (int j = 0; j < 8; j++) {
                        float s = wc[0]*t[j] + wc[1]*t[j+1] + wc[2]*t[j+2]
                                + wc[3]*t[j+3] + wc[4]*t[j+4];
                        o0[j] += s;
                    }
                    #pragma unroll
                    for (int v = 0; v < 5; v++) wp[v] = wc[v];
                }
            }
            float* ob = out + (size_t)b * HW + (size_t)(y0 + r) * IMG_W + x0 + c;
            *(float4*)ob               = make_float4(o0[0], o0[1], o0[2], o0[3]);
            *(float4*)(ob + 4)         = make_float4(o0[4], o0[5], o0[6], o0[7]);
            *(float4*)(ob + IMG_W)     = make_float4(o1[0], o1[1], o1[2], o1[3]);
            *(float4*)(ob + IMG_W + 4) = make_float4(o1[4], o1[5], o1[6], o1[7]);
        }
    } else {
        // ---- border path: staged stage 3 then stage 4 (exact clipping) ----
        if (tid < 17 * 9) {
            float w[9];
            #pragma unroll
            for (int i = 0; i < 9; i++) w[i] = wbuf[27 + i];
            int rp = tid / 9, g = tid - rp * 9;
            int r = rp * 2, c = g * 8;
            float v0[8] = {0,0,0,0,0,0,0,0}, v1[8] = {0,0,0,0,0,0,0,0};
            #pragma unroll
            for (int i = 0; i < 4; i++) {
                float t[12];
                *(float4*)&t[0] = *(const float4*)&sG[(r + i) * GP + c];
                *(float4*)&t[4] = *(const float4*)&sG[(r + i) * GP + c + 4];
                *(float4*)&t[8] = *(const float4*)&sG[(r + i) * GP + c + 8];
                if (i < 3) {
                    #pragma unroll
                    for (int j = 0; j < 8; j++)
                        v0[j] += w[i*3]*t[j] + w[i*3+1]*t[j+1] + w[i*3+2]*t[j+2];
                }
                if (i > 0) {
                    #pragma unroll
                    for (int j = 0; j < 8; j++)
                        v1[j] += w[(i-1)*3]*t[j] + w[(i-1)*3+1]*t[j+1] + w[(i-1)*3+2]*t[j+2];
                }
            }
            int py = y0 + r - 1, px = x0 + c - 1;
            bool iny0 = (unsigned)py       < (unsigned)IMG_H;
            bool iny1 = (unsigned)(py + 1) < (unsigned)IMG_H;
            #pragma unroll
            for (int j = 0; j < 8; j++) {
                bool inx = (unsigned)(px + j) < (unsigned)IMG_W;
                v0[j] = (iny0 && inx) ? v0[j] : 0.f;
                v1[j] = (iny1 && inx) ? v1[j] : 0.f;
            }
            *(float4*)&sT[r * TP + c]           = make_float4(v0[0], v0[1], v0[2], v0[3]);
            *(float4*)&sT[r * TP + c + 4]       = make_float4(v0[4], v0[5], v0[6], v0[7]);
            *(float4*)&sT[(r + 1) * TP + c]     = make_float4(v1[0], v1[1], v1[2], v1[3]);
            *(float4*)&sT[(r + 1) * TP + c + 4] = make_float4(v1[4], v1[5], v1[6], v1[7]);
        }
        __syncthreads();

        if (tid < 16 * 8) {
            float w[9];
            #pragma unroll
            for (int i = 0; i < 9; i++) w[i] = wbuf[36 + i];
            int rp = tid >> 3, g = tid & 7;
            int r = rp * 2, c = g * 8;
            float v0[8] = {0,0,0,0,0,0,0,0}, v1[8] = {0,0,0,0,0,0,0,0};
            #pragma unroll
            for (int i = 0; i < 4; i++) {
                float t[12];
                *(float4*)&t[0] = *(const float4*)&sT[(r + i) * TP + c];
                *(float4*)&t[4] = *(const float4*)&sT[(r + i) * TP + c + 4];
                *(float4*)&t[8] = *(const float4*)&sT[(r + i) * TP + c + 8];
                if (i < 3) {
                    #pragma unroll
                    for (int j = 0; j < 8; j++)
                        v0[j] += w[i*3]*t[j] + w[i*3+1]*t[j+1] + w[i*3+2]*t[j+2];
                }
                if (i > 0) {
                    #pragma unroll
                    for (int j = 0; j < 8; j++)
                        v1[j] += w[(i-1)*3]*t[j] + w[(i-1)*3+1]*t[j+1] + w[(i-1)*3+2]*t[j+2];
                }
            }
            float* ob = out + (size_t)b * HW + (size_t)(y0 + r) * IMG_W + x0 + c;
            *(float4*)ob                 = make_float4(v0[0], v0[1], v0[2], v0[3]);
            *(float4*)(ob + 4)           = make_float4(v0[4], v0[5], v0[6], v0[7]);
            *(float4*)(ob + IMG_W)       = make_float4(v1[0], v1[1], v1[2], v1[3]);
            *(float4*)(ob + IMG_W + 4)   = make_float4(v1[4], v1[5], v1[6], v1[7]);
        }
    }
}

extern "C" void kernel_launch(void* const* d_in, const int* in_sizes, int n_in,
                              void* d_out, int out_size) {
    const float* img = (const float*)d_in[0];
    const float* gw  = (const float*)d_in[1];
    const float* sxw = (const float*)d_in[2];
    const float* syw = (const float*)d_in[3];
    const float* dw  = (const float*)d_in[4];
    const float* nw  = (const float*)d_in[5];
    float* out = (float*)d_out;

    int C = in_sizes[1] / 9;
    if (C < 1) C = 1;
    int B = in_sizes[0] / (C * HW);
    if (B < 1) B = 1;

    dim3 grid(IMG_W / TW, IMG_H / TH, B);
    canny_fused<<<grid, NT>>>(img, gw, sxw, syw, dw, nw, out, C, 1.0f / (float)C);
}